// round 3
// baseline (speedup 1.0000x reference)
#include <cuda_runtime.h>
#include <math_constants.h>

// Problem constants (match reference setup_inputs)
#define NROWS 131072
#define D     128
#define NC    512

// Tiling
#define R_TILE   64          // rows per CTA
#define CHUNK    64          // codebook rows per smem chunk
#define THREADS  256

#define XS_STRIDE 130        // 128 + 2 pad (even, conflict-free for LDS.64)
#define CS_STRIDE 130
#define L_STRIDE  514        // 512 + 2 pad

#define SMEM_FLOATS (2 * R_TILE * XS_STRIDE + R_TILE * L_STRIDE)  // 49536
#define SMEM_BYTES  (SMEM_FLOATS * 4)                              // 198144

#define ARG_MARGIN 1e-5f

__device__ __forceinline__ void fma2(unsigned long long& acc,
                                     unsigned long long a,
                                     unsigned long long b) {
    asm("fma.rn.f32x2 %0, %1, %2, %0;" : "+l"(acc) : "l"(a), "l"(b));
}

__device__ __forceinline__ unsigned long long dup2(float v) {
    unsigned long long r;
    asm("mov.b64 %0, {%1, %1};" : "=l"(r) : "f"(v));
    return r;
}

__device__ __forceinline__ float2 unpack2(unsigned long long v) {
    float2 r;
    asm("mov.b64 {%0, %1}, %2;" : "=f"(r.x), "=f"(r.y) : "l"(v));
    return r;
}

__global__ void __launch_bounds__(THREADS)
gumbel_vq_kernel(const float* __restrict__ x,
                 const float* __restrict__ mask,
                 const float* __restrict__ codebook,
                 const float* __restrict__ noise,
                 float* __restrict__ out_q,    // (n, 128)
                 float* __restrict__ out_e,    // (n, 512)
                 float* __restrict__ out_i)    // (n,) indices as float
{
    extern __shared__ float sm[];
    float* xs = sm;                                  // [R_TILE][XS_STRIDE]
    float* cs = sm + R_TILE * XS_STRIDE;             // [CHUNK][CS_STRIDE]
    float* L  = sm + 2 * R_TILE * XS_STRIDE;         // [R_TILE][L_STRIDE]

    const int t    = threadIdx.x;
    const int row0 = blockIdx.x * R_TILE;

    // ---------------- Load x tile (with mask nudge) ----------------
    for (int f = t; f < R_TILE * D / 4; f += THREADS) {
        int r  = f >> 5;               // 32 float4 per row
        int c4 = (f & 31) << 2;
        float4 v = *reinterpret_cast<const float4*>(x + (size_t)(row0 + r) * D + c4);
        float nud = (1.0f - mask[row0 + r]) * 1e-6f;
        v.x += nud; v.y += nud; v.z += nud; v.w += nud;
        float* dst = xs + r * XS_STRIDE + c4;
        *reinterpret_cast<float2*>(dst)     = make_float2(v.x, v.y);
        *reinterpret_cast<float2*>(dst + 2) = make_float2(v.z, v.w);
    }
    __syncthreads();

    // ---------------- Row normalize (4 threads / row) ----------------
    // Norm in fp64 (a 1-ULP norm difference only scales the row -> order
    // preserving), but the per-element quotient is an fp32 IEEE division,
    // matching the reference's elementwise x / norm rounding.
    {
        int r = t >> 2, q = t & 3;
        float* xr = xs + r * XS_STRIDE + q * 32;
        double s = 0.0;
        #pragma unroll
        for (int k = 0; k < 32; k++) { double v = (double)xr[k]; s += v * v; }
        s += __shfl_xor_sync(0xFFFFFFFFu, s, 1);
        s += __shfl_xor_sync(0xFFFFFFFFu, s, 2);
        float nf = (float)sqrt(s);
        nf = fmaxf(nf, 1e-6f);
        #pragma unroll
        for (int k = 0; k < 32; k++) xr[k] = xr[k] / nf;   // IEEE fp32 div
    }
    __syncthreads();

    const int ty = t >> 4;   // 0..15 (row groups of 4)
    const int tx = t & 15;   // 0..15 (code/col groups)

    // ---------------- GEMM1: ab = xn @ C^T, write to L ----------------
    for (int cb = 0; cb < NC; cb += CHUNK) {
        for (int f = t; f < CHUNK * D / 4; f += THREADS) {
            int r  = f >> 5;
            int c4 = (f & 31) << 2;
            float4 v = *reinterpret_cast<const float4*>(codebook + (size_t)(cb + r) * D + c4);
            float* dst = cs + r * CS_STRIDE + c4;
            *reinterpret_cast<float2*>(dst)     = make_float2(v.x, v.y);
            *reinterpret_cast<float2*>(dst + 2) = make_float2(v.z, v.w);
        }
        __syncthreads();

        unsigned long long acc[4][4];
        #pragma unroll
        for (int i = 0; i < 4; i++)
            #pragma unroll
            for (int j = 0; j < 4; j++) acc[i][j] = 0ull;

        const float* xb = xs + (4 * ty) * XS_STRIDE;
        const float* cbp = cs + tx * CS_STRIDE;

        #pragma unroll 4
        for (int k2 = 0; k2 < 64; k2++) {
            unsigned long long a2[4], b2[4];
            #pragma unroll
            for (int i = 0; i < 4; i++)
                a2[i] = *reinterpret_cast<const unsigned long long*>(xb + i * XS_STRIDE + 2 * k2);
            #pragma unroll
            for (int j = 0; j < 4; j++)
                b2[j] = *reinterpret_cast<const unsigned long long*>(cbp + 16 * j * CS_STRIDE + 2 * k2);
            #pragma unroll
            for (int i = 0; i < 4; i++)
                #pragma unroll
                for (int j = 0; j < 4; j++)
                    fma2(acc[i][j], a2[i], b2[j]);
        }

        #pragma unroll
        for (int i = 0; i < 4; i++) {
            #pragma unroll
            for (int j = 0; j < 4; j++) {
                float2 p = unpack2(acc[i][j]);
                L[(4 * ty + i) * L_STRIDE + cb + tx + 16 * j] = p.x + p.y;
            }
        }
        __syncthreads();
    }

    // ---------------- Argmin (two-tier) + Softmax (4 threads / row) ----------------
    {
        int r = t >> 2, q = t & 3;
        const int gr = row0 + r;
        float* Lr = L + r * L_STRIDE + q * 128;
        const float* nz = noise + (size_t)gr * NC + q * 128;

        // --- tier 1: per-lane max1/max2 of ab over this lane's 128 codes ---
        float m1 = -CUDART_INF_F, m2 = -CUDART_INF_F;
        int i1 = 1 << 30;
        for (int k = 0; k < 128; k++) {
            float ab = Lr[k];
            int ci = q * 128 + k;
            if (ab > m1) { m2 = m1; m1 = ab; i1 = ci; }
            else         { m2 = fmaxf(m2, ab); }
        }
        // combine across the 4 lanes of this row
        #pragma unroll
        for (int dlt = 1; dlt <= 2; dlt <<= 1) {
            float om1 = __shfl_xor_sync(0xFFFFFFFFu, m1, dlt);
            float om2 = __shfl_xor_sync(0xFFFFFFFFu, m2, dlt);
            int   oi1 = __shfl_xor_sync(0xFFFFFFFFu, i1, dlt);
            if (om1 > m1)       { m2 = fmaxf(m1, om2); m1 = om1; i1 = oi1; }
            else if (om1 == m1) { m2 = m1; i1 = min(i1, oi1); }
            else                { m2 = fmaxf(m2, om1); }
        }

        int final_idx = i1;
        if (!(m1 - m2 > ARG_MARGIN)) {
            // --- tier 2: re-evaluate near-max candidates, REPLICATING the
            // reference's arithmetic: ab from a serial ascending-k fp32 FMA
            // chain (cuBLAS/Eigen accumulation order), then the exact
            // distance formula (1 - 2*ab) + 1, argmin with first-index ties.
            unsigned sub = 0xFu << ((t & 31) & ~3);   // this row's 4 lanes
            const float* xr = xs + r * XS_STRIDE;
            float bd = CUDART_INF_F;
            int bi = 1 << 30;
            float thresh = m1 - ARG_MARGIN;
            for (int k = 0; k < 128; k++) {
                if (Lr[k] >= thresh) {
                    const float* cj = codebook + (size_t)(q * 128 + k) * D;
                    float acc = 0.0f;
                    #pragma unroll 8
                    for (int kk = 0; kk < 128; kk++)
                        acc = fmaf(xr[kk], cj[kk], acc);   // serial ascending k
                    float df = (1.0f - 2.0f * acc) + 1.0f;
                    int ci = q * 128 + k;
                    if (df < bd || (df == bd && ci < bi)) { bd = df; bi = ci; }
                }
            }
            #pragma unroll
            for (int dlt = 1; dlt <= 2; dlt <<= 1) {
                float od = __shfl_xor_sync(sub, bd, dlt);
                int   oi = __shfl_xor_sync(sub, bi, dlt);
                if (od < bd || (od == bd && oi < bi)) { bd = od; bi = oi; }
            }
            final_idx = bi;
        }
        if (q == 0) out_i[gr] = (float)final_idx;

        // --- softmax pass A: logits v = 2*ab + noise, track max ---
        float m = -CUDART_INF_F;
        for (int k = 0; k < 128; k += 4) {
            int kk = (k + 8 * q) & 127;          // rotate to dodge smem bank conflicts
            float4 nv = *reinterpret_cast<const float4*>(nz + kk);
            float v0 = 2.0f * Lr[kk + 0] + nv.x;
            float v1 = 2.0f * Lr[kk + 1] + nv.y;
            float v2 = 2.0f * Lr[kk + 2] + nv.z;
            float v3 = 2.0f * Lr[kk + 3] + nv.w;
            Lr[kk + 0] = v0; Lr[kk + 1] = v1; Lr[kk + 2] = v2; Lr[kk + 3] = v3;
            m = fmaxf(m, fmaxf(fmaxf(v0, v1), fmaxf(v2, v3)));
        }
        m = fmaxf(m, __shfl_xor_sync(0xFFFFFFFFu, m, 1));
        m = fmaxf(m, __shfl_xor_sync(0xFFFFFFFFu, m, 2));

        // --- pass B: exp(v - m), accumulate sum ---
        float s = 0.f;
        for (int k = 0; k < 128; k++) {
            int kk = (k + 8 * q) & 127;
            float e = __expf(Lr[kk] - m);
            Lr[kk] = e;
            s += e;
        }
        s += __shfl_xor_sync(0xFFFFFFFFu, s, 1);
        s += __shfl_xor_sync(0xFFFFFFFFu, s, 2);
        float inv = 1.0f / s;

        // --- pass C: normalize, write encodings to smem (for GEMM2) and global ---
        float* ez = out_e + (size_t)gr * NC + q * 128;
        for (int k = 0; k < 128; k += 4) {
            int kk = (k + 8 * q) & 127;
            float4 ev;
            ev.x = Lr[kk + 0] * inv;
            ev.y = Lr[kk + 1] * inv;
            ev.z = Lr[kk + 2] * inv;
            ev.w = Lr[kk + 3] * inv;
            Lr[kk + 0] = ev.x; Lr[kk + 1] = ev.y; Lr[kk + 2] = ev.z; Lr[kk + 3] = ev.w;
            *reinterpret_cast<float4*>(ez + kk) = ev;
        }
    }

    // ---------------- GEMM2: quantized = enc @ C ----------------
    unsigned long long qa[4][4];
    #pragma unroll
    for (int i = 0; i < 4; i++)
        #pragma unroll
        for (int j = 0; j < 4; j++) qa[i][j] = 0ull;

    for (int cb = 0; cb < NC; cb += CHUNK) {
        __syncthreads();   // previous chunk consumers / softmax writes done
        for (int f = t; f < CHUNK * D / 4; f += THREADS) {
            int r  = f >> 5;
            int c4 = (f & 31) << 2;
            float4 v = *reinterpret_cast<const float4*>(codebook + (size_t)(cb + r) * D + c4);
            float* dst = cs + r * CS_STRIDE + c4;
            *reinterpret_cast<float2*>(dst)     = make_float2(v.x, v.y);
            *reinterpret_cast<float2*>(dst + 2) = make_float2(v.z, v.w);
        }
        __syncthreads();

        const float* Lb = L + (4 * ty) * L_STRIDE + cb;
        #pragma unroll 4
        for (int cc = 0; cc < CHUNK; cc++) {
            unsigned long long e2[4], b2[4];
            #pragma unroll
            for (int i = 0; i < 4; i++)
                e2[i] = dup2(Lb[i * L_STRIDE + cc]);
            #pragma unroll
            for (int j = 0; j < 4; j++)
                b2[j] = *reinterpret_cast<const unsigned long long*>(cs + cc * CS_STRIDE + 2 * tx + 32 * j);
            #pragma unroll
            for (int i = 0; i < 4; i++)
                #pragma unroll
                for (int j = 0; j < 4; j++)
                    fma2(qa[i][j], e2[i], b2[j]);
        }
    }

    #pragma unroll
    for (int i = 0; i < 4; i++) {
        #pragma unroll
        for (int j = 0; j < 4; j++) {
            float2 p = unpack2(qa[i][j]);
            *reinterpret_cast<float2*>(out_q + (size_t)(row0 + 4 * ty + i) * D + 2 * tx + 32 * j) = p;
        }
    }
}

extern "C" void kernel_launch(void* const* d_in, const int* in_sizes, int n_in,
                              void* d_out, int out_size) {
    const float* x        = (const float*)d_in[0];   // (131072, 128)
    const float* mask     = (const float*)d_in[1];   // (131072,)
    const float* codebook = (const float*)d_in[2];   // (512, 128)
    const float* noise    = (const float*)d_in[3];   // (131072, 512)

    float* out   = (float*)d_out;
    float* out_q = out;                                   // (n, 128)
    float* out_e = out + (size_t)NROWS * D;               // (n, 512)
    float* out_i = out_e + (size_t)NROWS * NC;            // (n,)

    cudaFuncSetAttribute(gumbel_vq_kernel,
                         cudaFuncAttributeMaxDynamicSharedMemorySize, SMEM_BYTES);

    dim3 grid(NROWS / R_TILE);
    gumbel_vq_kernel<<<grid, THREADS, SMEM_BYTES>>>(x, mask, codebook, noise,
                                                    out_q, out_e, out_i);
}